// round 1
// baseline (speedup 1.0000x reference)
#include <cuda_runtime.h>
#include <cuda_bf16.h>

// ---------------------------------------------------------------------------
// LRU forward on GB300.
//   Bu[b,l,n]   = sum_h u[b,l,h] * (exp(gamma[n]) * (Bp_re[n,h] + i Bp_im[n,h]))
//   x[b,l,n]    = lam[n] * x[b,l-1,n] + Bu[b,l,n],   x[b,-1]=0
//   pre[b,l]    = x[b,l-1]  (state BEFORE step l; pre[b,0]=0)
//   y[b,l,o]    = Re( sum_n pre[b,l,n]*C[o,n] ) + sum_h u[b,l,h]*D[o,h]
//   states[b,t] = [0, x[b,0], ..., x[b,L-1]]   (t = 0..L)
//
// Structure:
//   prep:   lam, lam^T, B(gamma-scaled, [h][n]), C^T packed float4, D^T float4
//   K1:     per (b,chunk): fused Bu GEMM tile + store Bu + local scan -> end
//   K2:     per (b,n): combine chunk ends across 64 chunks -> carry per chunk
//   K3:     per (b,chunk): rescan with carry, write states, fused y GEMM
// ---------------------------------------------------------------------------

#define BB   8
#define LL   8192
#define HH   128
#define NN   256
#define OO   128
#define TCH  128         // timesteps per chunk
#define NCH  (LL / TCH)  // 64 chunks
#define TS   16          // timesteps per subtile

// ------------------------- scratch (static device) -------------------------
__device__ float2 g_Bu[(size_t)BB * LL * NN];     // 16,777,216 float2 = 128 MiB
__device__ float2 g_Bmat[HH * NN];                // B^T: [h][n], gamma-scaled
__device__ float4 g_Ct4[(NN / 2) * OO];           // [n/2][o]: (Cre,Cim,Cre,Cim)
__device__ float4 g_Dt4[(HH / 4) * OO];           // [h/4][o]: D[o][h..h+3]
__device__ float2 g_lam[NN];
__device__ float2 g_lamT[NN];                     // lam^TCH
__device__ float2 g_end[BB * NCH * NN];
__device__ float2 g_carry[BB * NCH * NN];

// ------------------------------- prep ---------------------------------------
__global__ void prep_kernel(const float* __restrict__ nu_log,
                            const float* __restrict__ theta_log,
                            const float* __restrict__ gamma_log,
                            const float* __restrict__ Bp_re,
                            const float* __restrict__ Bp_im,
                            const float* __restrict__ C_re,
                            const float* __restrict__ C_im,
                            const float* __restrict__ D) {
    int idx = blockIdx.x * blockDim.x + threadIdx.x;   // 0..32767

    if (idx < NN) {
        float nu = expf(nu_log[idx]);
        float a  = expf(-nu);
        float th = expf(theta_log[idx]);
        g_lam[idx] = make_float2(a * cosf(th), a * sinf(th));
        double rT   = exp(-(double)nu * (double)TCH);
        double angT = (double)th * (double)TCH;
        g_lamT[idx] = make_float2((float)(rT * cos(angT)), (float)(rT * sin(angT)));
    }
    if (idx < HH * NN) {   // Bmat [h][n]
        int h = idx >> 8;
        int n = idx & (NN - 1);
        float g = expf(gamma_log[n]);
        g_Bmat[idx] = make_float2(g * Bp_re[n * HH + h], g * Bp_im[n * HH + h]);
    }
    if (idx < (NN / 2) * OO) {   // Ct4 [p][o]
        int p = idx >> 7;
        int o = idx & (OO - 1);
        int n0 = 2 * p;
        g_Ct4[idx] = make_float4(C_re[o * NN + n0],     C_im[o * NN + n0],
                                 C_re[o * NN + n0 + 1], C_im[o * NN + n0 + 1]);
    }
    if (idx < (HH / 4) * OO) {   // Dt4 [q][o]
        int q = idx >> 7;
        int o = idx & (OO - 1);
        g_Dt4[idx] = make_float4(D[o * HH + 4 * q],     D[o * HH + 4 * q + 1],
                                 D[o * HH + 4 * q + 2], D[o * HH + 4 * q + 3]);
    }
}

// -------------------- K1: Bu GEMM + local chunk scan ------------------------
__global__ __launch_bounds__(256) void bu_scan_kernel(const float* __restrict__ u) {
    __shared__ __align__(16) float su[TS][HH];   // 8 KB

    const int c = blockIdx.x;     // chunk
    const int b = blockIdx.y;     // batch
    const int n = threadIdx.x;    // state index

    const float2 lam = g_lam[n];
    float2 x = make_float2(0.f, 0.f);
    const int l0 = c * TCH;
    const float* ub = u + ((size_t)b * LL + l0) * HH;

    for (int sub = 0; sub < TCH / TS; ++sub) {
        __syncthreads();
        // cooperative load of the u subtile (contiguous TS*HH floats)
        {
            const float4* src = (const float4*)(ub + (size_t)sub * TS * HH);
            float4* dst = (float4*)&su[0][0];
            #pragma unroll
            for (int i = 0; i < (TS * HH / 4) / 256; ++i)
                dst[n + i * 256] = src[n + i * 256];
        }
        __syncthreads();

        float ar[TS], ai[TS];
        #pragma unroll
        for (int j = 0; j < TS; ++j) { ar[j] = 0.f; ai[j] = 0.f; }

        #pragma unroll 2
        for (int h4 = 0; h4 < HH; h4 += 4) {
            float2 b0 = g_Bmat[(h4 + 0) * NN + n];
            float2 b1 = g_Bmat[(h4 + 1) * NN + n];
            float2 b2 = g_Bmat[(h4 + 2) * NN + n];
            float2 b3 = g_Bmat[(h4 + 3) * NN + n];
            #pragma unroll
            for (int j = 0; j < TS; ++j) {
                float4 uv = *(const float4*)&su[j][h4];
                ar[j] = fmaf(uv.x, b0.x, ar[j]);  ai[j] = fmaf(uv.x, b0.y, ai[j]);
                ar[j] = fmaf(uv.y, b1.x, ar[j]);  ai[j] = fmaf(uv.y, b1.y, ai[j]);
                ar[j] = fmaf(uv.z, b2.x, ar[j]);  ai[j] = fmaf(uv.z, b2.y, ai[j]);
                ar[j] = fmaf(uv.w, b3.x, ar[j]);  ai[j] = fmaf(uv.w, b3.y, ai[j]);
            }
        }

        // store Bu + advance local scan (zero-init)
        size_t base = ((size_t)b * LL + l0 + sub * TS) * NN + n;
        #pragma unroll
        for (int j = 0; j < TS; ++j) {
            float2 v = make_float2(ar[j], ai[j]);
            g_Bu[base + (size_t)j * NN] = v;
            float nr = fmaf(lam.x, x.x, fmaf(-lam.y, x.y, v.x));
            float ni = fmaf(lam.x, x.y, fmaf( lam.y, x.x, v.y));
            x = make_float2(nr, ni);
        }
    }
    g_end[((size_t)b * NCH + c) * NN + n] = x;
}

// ----------------- K2: combine chunk ends -> per-chunk carries ---------------
__global__ void carry_kernel() {
    const int b = blockIdx.x;
    const int n = threadIdx.x;
    const float2 lamT = g_lamT[n];
    float2 x = make_float2(0.f, 0.f);
    for (int ch = 0; ch < NCH; ++ch) {
        size_t i = ((size_t)b * NCH + ch) * NN + n;
        g_carry[i] = x;                       // state ENTERING chunk ch
        float2 e = g_end[i];
        float nr = fmaf(lamT.x, x.x, fmaf(-lamT.y, x.y, e.x));
        float ni = fmaf(lamT.x, x.y, fmaf( lamT.y, x.x, e.y));
        x = make_float2(nr, ni);
    }
}

// --------- K3: final scan + states output + fused y projection ---------------
__global__ __launch_bounds__(256) void out_kernel(const float* __restrict__ u,
                                                  float* __restrict__ yout,
                                                  float2* __restrict__ stc,
                                                  float* __restrict__ str) {
    __shared__ __align__(16) float2 pre_s[TS][NN];   // 32 KB
    __shared__ __align__(16) float  su[TS][HH];      //  8 KB

    const int c   = blockIdx.x;
    const int b   = blockIdx.y;
    const int tid = threadIdx.x;
    const int n   = tid;
    const int group = tid >> 7;       // 0/1: which 8 timesteps of the subtile
    const int o     = tid & (OO - 1); // output channel

    const float2 lam = g_lam[n];
    float2 x = g_carry[((size_t)b * NCH + c) * NN + n];
    const int l0 = c * TCH;

    for (int sub = 0; sub < TCH / TS; ++sub) {
        const int lbase = l0 + sub * TS;
        __syncthreads();
        // load u subtile
        {
            const float4* src = (const float4*)(u + ((size_t)b * LL + lbase) * HH);
            float4* dst = (float4*)&su[0][0];
            #pragma unroll
            for (int i = 0; i < (TS * HH / 4) / 256; ++i)
                dst[tid + i * 256] = src[tid + i * 256];
        }
        // scan: publish pre-states, optionally write states output
        {
            size_t bub = ((size_t)b * LL + lbase) * NN + n;
            size_t stb = ((size_t)b * (LL + 1) + lbase) * NN + n;
            #pragma unroll
            for (int j = 0; j < TS; ++j) {
                pre_s[j][n] = x;
                if (stc) stc[stb + (size_t)j * NN] = x;
                if (str) str[stb + (size_t)j * NN] = x.x;
                float2 v = g_Bu[bub + (size_t)j * NN];
                float nr = fmaf(lam.x, x.x, fmaf(-lam.y, x.y, v.x));
                float ni = fmaf(lam.x, x.y, fmaf( lam.y, x.x, v.y));
                x = make_float2(nr, ni);
            }
        }
        __syncthreads();

        if (yout) {
            float acc[8];
            #pragma unroll
            for (int j = 0; j < 8; ++j) acc[j] = 0.f;

            // y += Re(pre * C): complex dot over n (pairs of states per iter)
            #pragma unroll 2
            for (int p = 0; p < NN / 2; ++p) {
                float4 c4 = g_Ct4[p * OO + o];
                #pragma unroll
                for (int j = 0; j < 8; ++j) {
                    float4 pp = *(const float4*)&pre_s[group * 8 + j][2 * p];
                    acc[j] = fmaf( pp.x, c4.x, acc[j]);
                    acc[j] = fmaf(-pp.y, c4.y, acc[j]);
                    acc[j] = fmaf( pp.z, c4.z, acc[j]);
                    acc[j] = fmaf(-pp.w, c4.w, acc[j]);
                }
            }
            // y += u @ D^T
            #pragma unroll 2
            for (int q = 0; q < HH / 4; ++q) {
                float4 d4 = g_Dt4[q * OO + o];
                #pragma unroll
                for (int j = 0; j < 8; ++j) {
                    float4 uv = *(const float4*)&su[group * 8 + j][4 * q];
                    acc[j] = fmaf(uv.x, d4.x, acc[j]);
                    acc[j] = fmaf(uv.y, d4.y, acc[j]);
                    acc[j] = fmaf(uv.z, d4.z, acc[j]);
                    acc[j] = fmaf(uv.w, d4.w, acc[j]);
                }
            }
            #pragma unroll
            for (int j = 0; j < 8; ++j) {
                int l = lbase + group * 8 + j;
                yout[((size_t)b * LL + l) * OO + o] = acc[j];
            }
        }
    }

    // final state -> states[b][L]
    if (c == NCH - 1) {
        if (stc) stc[((size_t)b * (LL + 1) + LL) * NN + n] = x;
        if (str) str[((size_t)b * (LL + 1) + LL) * NN + n] = x.x;
    }
}

// ------------------------------ launch ---------------------------------------
extern "C" void kernel_launch(void* const* d_in, const int* in_sizes, int n_in,
                              void* d_out, int out_size) {
    const float* u         = (const float*)d_in[0];
    const float* nu_log    = (const float*)d_in[1];
    const float* theta_log = (const float*)d_in[2];
    const float* gamma_log = (const float*)d_in[3];
    const float* Bp_re     = (const float*)d_in[4];
    const float* Bp_im     = (const float*)d_in[5];
    const float* C_re      = (const float*)d_in[6];
    const float* C_im      = (const float*)d_in[7];
    const float* D         = (const float*)d_in[8];

    float* out = (float*)d_out;

    const long long NY  = (long long)BB * LL * OO;          // 8,388,608 (y floats)
    const long long NSc = (long long)BB * (LL + 1) * NN;    // 16,779,264 (states cplx)
    const long long osz = (long long)out_size;

    float*  yout = nullptr;
    float2* stc  = nullptr;   // states as interleaved (re, im)
    float*  str  = nullptr;   // states real part only

    if (osz == NY) {
        yout = out;                                          // y only
    } else if (osz == NY + 2 * NSc) {
        yout = out; stc = (float2*)(out + NY);               // y + states (float pairs)
    } else if (osz == 2 * NSc) {
        stc = (float2*)out;                                  // states only (float pairs)
    } else if (osz == NSc) {
        stc = (float2*)out;                                  // states only (complex64 count)
    } else if (osz == NY + NSc) {
        yout = out; str = out + NY;                          // y + Re(states)
    } else {
        yout = out;                                          // best effort
    }

    prep_kernel<<<128, 256>>>(nu_log, theta_log, gamma_log,
                              Bp_re, Bp_im, C_re, C_im, D);
    bu_scan_kernel<<<dim3(NCH, BB), 256>>>(u);
    carry_kernel<<<BB, 256>>>();
    out_kernel<<<dim3(NCH, BB), 256>>>(u, yout, stc, str);
}